// round 9
// baseline (speedup 1.0000x reference)
#include <cuda_runtime.h>
#include <cuda_bf16.h>
#include <cstdint>

#define DD   128
#define NN   21845          // (4^8 - 1) / 3
#define NPOS 18
#define NDEP 46
#define NMAT (NPOS + NDEP)

__host__ __device__ __forceinline__ int lvl_start(int l) {
    return ((1 << (2 * l)) - 1) / 3;
}

typedef unsigned long long ull;

// ---------------- FFMA2 helpers (narrow kernel) ----------------
__device__ __forceinline__ void fma2(ull& acc, ull a, ull b) {
    asm("fma.rn.f32x2 %0, %1, %2, %0;" : "+l"(acc) : "l"(a), "l"(b));
}
__device__ __forceinline__ void unpack2(ull v, float& lo, float& hi) {
    asm("mov.b64 {%0, %1}, %2;" : "=f"(lo), "=f"(hi) : "l"(v));
}
__device__ __forceinline__ float4 max4(float4 a, float4 b) {
    float4 r;
    r.x = fmaxf(a.x, b.x); r.y = fmaxf(a.y, b.y);
    r.z = fmaxf(a.z, b.z); r.w = fmaxf(a.w, b.w);
    return r;
}
__device__ __forceinline__ unsigned sw16(unsigned b) {
    return b ^ ((b >> 3) & 0x10u);
}

// ---------------- HMMA m16n8k16 bf16 (base-family PTX, sm_80+) ----------------
__device__ __forceinline__ void mma16816(float& d0, float& d1, float& d2, float& d3,
                                         uint32_t a0, uint32_t a1, uint32_t a2,
                                         uint32_t a3, uint32_t b0, uint32_t b1) {
    asm volatile(
        "mma.sync.aligned.m16n8k16.row.col.f32.bf16.bf16.f32 "
        "{%0,%1,%2,%3}, {%4,%5,%6,%7}, {%8,%9}, {%0,%1,%2,%3};"
        : "+f"(d0), "+f"(d1), "+f"(d2), "+f"(d3)
        : "r"(a0), "r"(a1), "r"(a2), "r"(a3), "r"(b0), "r"(b1));
}

// ---------------- persistent scratch ----------------
__device__ float g_xz[NN * DD];
__device__ float g_u[NN * DD];
// per matrix: WT hi [e][k] 128x128 bf16 (16384), then WT lo (16384)
__device__ __nv_bfloat16 g_wsp[(size_t)NMAT * 32768];
__device__ int   g_pos_perm[NN];
__device__ int   g_pos_off[NPOS + 1];
__device__ int   g_pos_tg[320], g_pos_tb[320];
__device__ int   g_pos_nt;
__device__ int   g_dep_perm[NN];
__device__ int   g_dep_off[7][NDEP + 1];
__device__ int   g_dep_tg[7][320], g_dep_tb[7][320];
__device__ int   g_dep_nt[7];
__device__ unsigned g_bar_cnt;
__device__ unsigned g_bar_gen;

__device__ __forceinline__ void gridbar(int nb) {
    __syncthreads();
    if (threadIdx.x == 0) {
        __threadfence();
        unsigned gen = *(volatile unsigned*)&g_bar_gen;
        if (atomicAdd(&g_bar_cnt, 1u) == (unsigned)nb - 1u) {
            atomicExch(&g_bar_cnt, 0u);
            __threadfence();
            atomicAdd(&g_bar_gen, 1u);
        } else {
            while (*(volatile unsigned*)&g_bar_gen == gen) __nanosleep(64);
        }
        __threadfence();
    }
    __syncthreads();
}

// ---------------------------------------------------------------------------
// Grouping: block 0 = pos (BM=128), blocks 1..7 = dep level b-1
// (BM=128 for levels 5,6; BM=16 for 0..4)
// ---------------------------------------------------------------------------
__global__ void group_kernel(const int* __restrict__ pos_ids,
                             const int* __restrict__ dep_ids) {
    __shared__ int cnt[NDEP];
    __shared__ int off[NDEP + 1];
    int t = threadIdx.x, lane = t & 31;
    const int* ids; int n, ng, base, BM;
    int *perm, *goff, *tg, *tb, *nt_out;
    if (blockIdx.x == 0) {
        ids = pos_ids; n = NN; ng = NPOS; base = 0; BM = 128;
        perm = g_pos_perm; goff = g_pos_off;
        tg = g_pos_tg; tb = g_pos_tb; nt_out = &g_pos_nt;
    } else {
        int l = blockIdx.x - 1;
        base = lvl_start(l + 1); n = 1 << (2 * (l + 1)); ng = NDEP;
        BM = (l >= 5) ? 128 : 16;
        ids = dep_ids + base; perm = g_dep_perm + base; goff = g_dep_off[l];
        tg = g_dep_tg[l]; tb = g_dep_tb[l]; nt_out = &g_dep_nt[l];
    }
    if (t < ng) cnt[t] = 0;
    __syncthreads();
    for (int i0 = 0; i0 < n; i0 += blockDim.x) {
        int i = i0 + t; bool v = (i < n);
        unsigned act = __ballot_sync(0xffffffffu, v);
        if (v) {
            int id = ids[i];
            unsigned m = __match_any_sync(act, id);
            if (lane == __ffs(m) - 1) atomicAdd(&cnt[id], __popc(m));
        }
    }
    __syncthreads();
    if (t == 0) {
        int s = 0;
        for (int j = 0; j < ng; ++j) { off[j] = s; s += cnt[j]; }
        off[ng] = s;
        int nt = 0;
        for (int j = 0; j < ng; ++j) {
            int c = off[j + 1] - off[j];
            for (int k = 0; k < c; k += BM) { tg[nt] = j; tb[nt] = off[j] + k; ++nt; }
        }
        *nt_out = nt;
        for (int j = 0; j <= ng; ++j) goff[j] = off[j];
    }
    __syncthreads();
    if (t < ng) cnt[t] = off[t];
    __syncthreads();
    for (int i0 = 0; i0 < n; i0 += blockDim.x) {
        int i = i0 + t; bool v = (i < n);
        unsigned act = __ballot_sync(0xffffffffu, v);
        if (v) {
            int id = ids[i];
            unsigned m = __match_any_sync(act, id);
            int leader = __ffs(m) - 1;
            int prior = __popc(m & ((1u << lane) - 1u));
            int bp = 0;
            if (lane == leader) bp = atomicAdd(&cnt[id], __popc(m));
            bp = __shfl_sync(act, bp, leader);
            perm[bp + prior] = base + i;
        }
    }
}

// ---------------------------------------------------------------------------
// W pre-split: transpose W[d][e] -> WT[e][d], split fp32 -> bf16 hi/lo, linear.
// Two 64-row passes through a 64x132 smem buffer (fits 48KB static).
// ---------------------------------------------------------------------------
__global__ __launch_bounds__(128)
void presplit_kernel(const float* __restrict__ pos_W,
                     const float* __restrict__ dep_W) {
    int j = blockIdx.x;
    const float* Wsrc = (j < NPOS) ? pos_W + (size_t)j * 16384
                                   : dep_W + (size_t)(j - NPOS) * 16384;
    __shared__ float sw[64 * 132];
    int t = threadIdx.x;   // = output row e
    uint32_t* hi = (uint32_t*)(g_wsp + (size_t)j * 32768);
    uint32_t* lo = (uint32_t*)(g_wsp + (size_t)j * 32768 + 16384);
    for (int r = 0; r < 2; ++r) {
        __syncthreads();
        for (int idx = t; idx < 64 * 128; idx += 128) {
            int d = idx >> 7, e2 = idx & 127;
            sw[d * 132 + e2] = Wsrc[(r * 64 + d) * 128 + e2];
        }
        __syncthreads();
#pragma unroll 4
        for (int d0 = 0; d0 < 64; d0 += 2) {
            float x0 = sw[d0 * 132 + t];
            float x1 = sw[(d0 + 1) * 132 + t];
            __nv_bfloat16 h0 = __float2bfloat16(x0);
            __nv_bfloat16 h1 = __float2bfloat16(x1);
            __nv_bfloat162 hp; hp.x = h0; hp.y = h1;
            __nv_bfloat162 lp;
            lp.x = __float2bfloat16(x0 - __bfloat162float(h0));
            lp.y = __float2bfloat16(x1 - __bfloat162float(h1));
            int u32idx = (t * 128 + r * 64 + d0) >> 1;
            hi[u32idx] = *(uint32_t*)&hp;
            lo[u32idx] = *(uint32_t*)&lp;
        }
    }
}

// ---------------------------------------------------------------------------
// HMMA tile: 128 rows x 128 cols x K=128, bf16 split 3-pass, 256 threads.
// 8 warps: warp w -> rows (w&3)*32..+31, cols (w>>2)*64..+63.
// smem (bytes): [0,512) sNode, [512,1024) sBias,
//   [1024) Ah 34816, Al, Wh, Wl  (each 128 rows x 136 bf16 = stride 68 b32)
// mode 0: A=emb -> g_xz; mode 1: A=g_xz -> g_u; mode 2: A=max(x,u-kids) -> g_u
// ---------------------------------------------------------------------------
#define TSTR 68                       // row stride in b32 (136 bf16)
#define TROW 272                      // row stride in bytes
#define OFF_AH 1024
#define OFF_AL (OFF_AH + 34816)
#define OFF_WH (OFF_AL + 34816)
#define OFF_WL (OFF_WH + 34816)
#define SMEM_T (OFF_WL + 34816)

__global__ __launch_bounds__(256, 1)
void tile_mma(int mode, int woff,
              const float* __restrict__ bias, const float* __restrict__ srcA,
              const int* __restrict__ nt_p, const int* __restrict__ tg,
              const int* __restrict__ tb, const int* __restrict__ off,
              const int* __restrict__ perm, int cs_row, int cs_child)
{
    int tile = blockIdx.x;
    if (tile >= *nt_p) return;
    extern __shared__ __align__(16) char smem[];
    int*   sNode = (int*)smem;
    float* sBias = (float*)(smem + 512);
    int t = threadIdx.x;
    int j = tg[tile], b0 = tb[tile];
    int mc = off[j + 1] - b0; if (mc > 128) mc = 128;
    if (t < 128) {
        sNode[t] = perm[b0 + min(t, mc - 1)];
        sBias[t] = bias[j * 128 + t];
    }

    // --- W staging: linear copy into stride-136 rows (hi & lo) ---
    {
        const uint4* srcH = (const uint4*)(g_wsp + (size_t)(woff + j) * 32768);
        const uint4* srcL = srcH + 2048;
#pragma unroll
        for (int i = 0; i < 8; ++i) {
            int idx = t + 256 * i;           // 0..2047 uint4
            int r = idx >> 4, c = idx & 15;  // row e, 16B chunk
            *(uint4*)(smem + OFF_WH + r * TROW + 16 * c) = srcH[idx];
            *(uint4*)(smem + OFF_WL + r * TROW + 16 * c) = srcL[idx];
        }
    }
    // --- A staging: gather row (+max over kids), split hi/lo ---
    {
        const float4* X4 = (const float4*)srcA;
        const float4* U4 = (const float4*)g_u;
#pragma unroll
        for (int i = 0; i < 16; ++i) {
            int idx = t + 256 * i;            // 0..4095
            int r = idx >> 5, c = idx & 31;   // row, float4 col
            int node = sNode[r];
            float4 v = X4[(size_t)node * 32 + c];
            if (mode == 2) {
                int ch = cs_child + 4 * (node - cs_row);
                v = max4(v, U4[(size_t)(ch + 0) * 32 + c]);
                v = max4(v, U4[(size_t)(ch + 1) * 32 + c]);
                v = max4(v, U4[(size_t)(ch + 2) * 32 + c]);
                v = max4(v, U4[(size_t)(ch + 3) * 32 + c]);
            }
            __nv_bfloat16 h0 = __float2bfloat16(v.x), h1 = __float2bfloat16(v.y);
            __nv_bfloat16 h2 = __float2bfloat16(v.z), h3 = __float2bfloat16(v.w);
            __nv_bfloat162 ha; ha.x = h0; ha.y = h1;
            __nv_bfloat162 hb; hb.x = h2; hb.y = h3;
            __nv_bfloat162 la, lb;
            la.x = __float2bfloat16(v.x - __bfloat162float(h0));
            la.y = __float2bfloat16(v.y - __bfloat162float(h1));
            lb.x = __float2bfloat16(v.z - __bfloat162float(h2));
            lb.y = __float2bfloat16(v.w - __bfloat162float(h3));
            uint2 hh; hh.x = *(uint32_t*)&ha; hh.y = *(uint32_t*)&hb;
            uint2 ll; ll.x = *(uint32_t*)&la; ll.y = *(uint32_t*)&lb;
            *(uint2*)(smem + OFF_AH + r * TROW + 8 * c) = hh;
            *(uint2*)(smem + OFF_AL + r * TROW + 8 * c) = ll;
        }
    }
    __syncthreads();

    int lane = t & 31, warp = t >> 5;
    int g = lane >> 2, tid = lane & 3;
    int m0 = (warp & 3) * 32, n0 = (warp >> 2) * 64;

    float acc[2][8][4];
#pragma unroll
    for (int mt = 0; mt < 2; ++mt)
#pragma unroll
        for (int nt = 0; nt < 8; ++nt)
#pragma unroll
            for (int q = 0; q < 4; ++q) acc[mt][nt][q] = 0.f;

    const uint32_t* Ah = (const uint32_t*)(smem + OFF_AH);
    const uint32_t* Al = (const uint32_t*)(smem + OFF_AL);
    const uint32_t* Wh = (const uint32_t*)(smem + OFF_WH);
    const uint32_t* Wl = (const uint32_t*)(smem + OFF_WL);

#pragma unroll
    for (int pass = 0; pass < 3; ++pass) {
        const uint32_t* As = (pass == 2) ? Al : Ah;
        const uint32_t* Ws = (pass == 1) ? Wl : Wh;
#pragma unroll
        for (int k16 = 0; k16 < 8; ++k16) {
            int kb = k16 * 8;
            uint32_t a[2][4];
#pragma unroll
            for (int mt = 0; mt < 2; ++mt) {
                int r = m0 + 16 * mt;
                a[mt][0] = As[(r + g) * TSTR + kb + tid];
                a[mt][1] = As[(r + g + 8) * TSTR + kb + tid];
                a[mt][2] = As[(r + g) * TSTR + kb + tid + 4];
                a[mt][3] = As[(r + g + 8) * TSTR + kb + tid + 4];
            }
#pragma unroll
            for (int nt = 0; nt < 8; ++nt) {
                int e = n0 + 8 * nt + g;
                uint32_t bb0 = Ws[e * TSTR + kb + tid];
                uint32_t bb1 = Ws[e * TSTR + kb + tid + 4];
                mma16816(acc[0][nt][0], acc[0][nt][1], acc[0][nt][2], acc[0][nt][3],
                         a[0][0], a[0][1], a[0][2], a[0][3], bb0, bb1);
                mma16816(acc[1][nt][0], acc[1][nt][1], acc[1][nt][2], acc[1][nt][3],
                         a[1][0], a[1][1], a[1][2], a[1][3], bb0, bb1);
            }
        }
    }

    // --- epilogue: bias + relu + direct STG ---
    float* base = (mode == 0) ? g_xz : g_u;
#pragma unroll
    for (int mt = 0; mt < 2; ++mt) {
        int row = m0 + 16 * mt + g;
        int nodeA = sNode[row];
        int nodeB = sNode[row + 8];
#pragma unroll
        for (int nt = 0; nt < 8; ++nt) {
            int c0 = n0 + 8 * nt + 2 * tid;
            float bx = sBias[c0], by = sBias[c0 + 1];
            float2 oA, oB;
            oA.x = fmaxf(acc[mt][nt][0] + bx, 0.f);
            oA.y = fmaxf(acc[mt][nt][1] + by, 0.f);
            oB.x = fmaxf(acc[mt][nt][2] + bx, 0.f);
            oB.y = fmaxf(acc[mt][nt][3] + by, 0.f);
            *(float2*)&base[(size_t)nodeA * 128 + c0] = oA;
            *(float2*)&base[(size_t)nodeB * 128 + c0] = oB;
        }
    }
}

// ---------------------------------------------------------------------------
// Narrow persistent kernel: dep levels 4..0 (packed-k FFMA2), root finalize.
// ---------------------------------------------------------------------------
__global__ __launch_bounds__(256, 2)
void narrow_all(const float* __restrict__ Wsrc, const float* __restrict__ bias,
                float* __restrict__ out)
{
    __shared__ __align__(16) char sWn[64 * 256];
    __shared__ __align__(16) float sA2[16 * 128];
    __shared__ int sN[16];
    int t = threadIdx.x;
    int nb = gridDim.x;
    for (int l = 4; l >= 0; --l) {
        int cs_row = lvl_start(l + 1);
        int cs_child = lvl_start(l + 2);
        int nt = g_dep_nt[l];
        int items = nt * 4;
        const int* tg = g_dep_tg[l];
        const int* tb = g_dep_tb[l];
        const int* off = g_dep_off[l];
        for (int item = blockIdx.x; item < items; item += nb) {
            __syncthreads();
            int tile = item >> 2, slice = item & 3, c0 = slice * 32;
            int j = tg[tile], b0 = tb[tile];
            int mc = off[j + 1] - b0; if (mc > 16) mc = 16;
            if (t < 16) sN[t] = g_dep_perm[cs_row + b0 + min(t, mc - 1)];
            const float* Wj = Wsrc + (size_t)j * 16384;
#pragma unroll
            for (int i = 0; i < 2; ++i) {
                int idx = t + 256 * i;
                int kp = idx >> 3, cb = idx & 7;
                float4 r0 = *(const float4*)&Wj[(2 * kp) * 128 + c0 + 4 * cb];
                float4 r1 = *(const float4*)&Wj[(2 * kp + 1) * 128 + c0 + 4 * cb];
                float4 s0 = make_float4(r0.x, r1.x, r0.y, r1.y);
                float4 s1 = make_float4(r0.z, r1.z, r0.w, r1.w);
                unsigned b = (unsigned)(kp * 256 + cb * 32);
                *(float4*)(sWn + sw16(b))      = s0;
                *(float4*)(sWn + sw16(b + 16)) = s1;
            }
            __syncthreads();
            const float4* X4 = (const float4*)g_xz;
            const float4* U4 = (const float4*)g_u;
#pragma unroll
            for (int i = 0; i < 2; ++i) {
                int idx = t + 256 * i; int r = idx >> 5, c = idx & 31;
                int node = sN[r];
                int ch = cs_child + 4 * (node - cs_row);
                float4 v = X4[(size_t)node * 32 + c];
                v = max4(v, U4[(size_t)(ch + 0) * 32 + c]);
                v = max4(v, U4[(size_t)(ch + 1) * 32 + c]);
                v = max4(v, U4[(size_t)(ch + 2) * 32 + c]);
                v = max4(v, U4[(size_t)(ch + 3) * 32 + c]);
                ((float4*)(sA2 + r * 128))[c] = v;
            }
            __syncthreads();
            int r = t >> 4, x16 = t & 15;
            ull accA = 0ull, accB = 0ull;
#pragma unroll 4
            for (int kp = 0; kp < 64; ++kp) {
                ull a = *(const ull*)&sA2[r * 128 + 2 * kp];
                ulonglong2 w = *(const ulonglong2*)(sWn + sw16((unsigned)(kp * 256 + x16 * 16)));
                fma2(accA, a, w.x);
                fma2(accB, a, w.y);
            }
            int node = sN[r];
            int col = c0 + 2 * x16;
            float2 bv = *(const float2*)&bias[j * 128 + col];
            float lo, hi; float2 o;
            unpack2(accA, lo, hi); o.x = fmaxf(lo + hi + bv.x, 0.f);
            unpack2(accB, lo, hi); o.y = fmaxf(lo + hi + bv.y, 0.f);
            *(float2*)&g_u[(size_t)node * 128 + col] = o;
        }
        gridbar(nb);
    }
    if (blockIdx.x == 0 && t < 32) {
        const float4* X4 = (const float4*)g_xz;
        const float4* U4 = (const float4*)g_u;
        float4 v = X4[t];
        v = max4(v, U4[1 * 32 + t]);
        v = max4(v, U4[2 * 32 + t]);
        v = max4(v, U4[3 * 32 + t]);
        v = max4(v, U4[4 * 32 + t]);
        ((float4*)out)[t] = v;
    }
}

// ---------------------------------------------------------------------------
extern "C" void kernel_launch(void* const* d_in, const int* in_sizes, int n_in,
                              void* d_out, int out_size) {
    const float* emb     = (const float*)d_in[0];
    const int*   pos_ids = (const int*)d_in[1];
    const int*   dep_ids = (const int*)d_in[2];
    const float* pos_W   = (const float*)d_in[3];
    const float* pos_b   = (const float*)d_in[4];
    const float* dep_W   = (const float*)d_in[5];
    const float* dep_b   = (const float*)d_in[6];

    cudaFuncSetAttribute(tile_mma, cudaFuncAttributeMaxDynamicSharedMemorySize,
                         SMEM_T);

    int *d_pos_nt, *d_pos_tg, *d_pos_tb, *d_pos_off, *d_pos_perm;
    int *d_dep_nt, *d_dep_tg, *d_dep_tb, *d_dep_off, *d_dep_perm;
    cudaGetSymbolAddress((void**)&d_pos_nt,   g_pos_nt);
    cudaGetSymbolAddress((void**)&d_pos_tg,   g_pos_tg);
    cudaGetSymbolAddress((void**)&d_pos_tb,   g_pos_tb);
    cudaGetSymbolAddress((void**)&d_pos_off,  g_pos_off);
    cudaGetSymbolAddress((void**)&d_pos_perm, g_pos_perm);
    cudaGetSymbolAddress((void**)&d_dep_nt,   g_dep_nt);
    cudaGetSymbolAddress((void**)&d_dep_tg,   g_dep_tg);
    cudaGetSymbolAddress((void**)&d_dep_tb,   g_dep_tb);
    cudaGetSymbolAddress((void**)&d_dep_off,  g_dep_off);
    cudaGetSymbolAddress((void**)&d_dep_perm, g_dep_perm);
    float* d_xz;
    cudaGetSymbolAddress((void**)&d_xz, g_xz);

    group_kernel<<<8, 1024>>>(pos_ids, dep_ids);
    presplit_kernel<<<NMAT, 128>>>(pos_W, dep_W);

    // pos: all NN nodes -> g_xz
    tile_mma<<<208, 256, SMEM_T>>>(0, 0, pos_b, emb,
        d_pos_nt, d_pos_tg, d_pos_tb, d_pos_off, d_pos_perm, 0, 0);

    // dep level 6: rows = level-7 nodes (z = x) -> g_u
    tile_mma<<<174, 256, SMEM_T>>>(1, NPOS, dep_b, d_xz,
        d_dep_nt + 6, d_dep_tg + 6 * 320, d_dep_tb + 6 * 320,
        d_dep_off + 6 * (NDEP + 1), d_dep_perm + lvl_start(7),
        lvl_start(7), 0);

    // dep level 5: rows = level-6 nodes, fused max-gather -> g_u
    tile_mma<<<78, 256, SMEM_T>>>(2, NPOS, dep_b, d_xz,
        d_dep_nt + 5, d_dep_tg + 5 * 320, d_dep_tb + 5 * 320,
        d_dep_off + 5 * (NDEP + 1), d_dep_perm + lvl_start(6),
        lvl_start(6), lvl_start(7));

    // levels 4..0 + root finalize in one persistent kernel
    int dev = 0, nsm = 0, occ = 0;
    cudaGetDevice(&dev);
    cudaDeviceGetAttribute(&nsm, cudaDevAttrMultiProcessorCount, dev);
    cudaOccupancyMaxActiveBlocksPerMultiprocessor(&occ, narrow_all, 256, 0);
    if (occ < 1) occ = 1;
    int grid = nsm * (occ < 2 ? occ : 2);
    narrow_all<<<grid, 256>>>(dep_W, dep_b, (float*)d_out);
}